// round 13
// baseline (speedup 1.0000x reference)
#include <cuda_runtime.h>
#include <math.h>
#include <stdint.h>

#define VOCAB 50000
#define EMBD  128
#define SLEN  200
#define TLEN  32
#define BATCH 64
#define QLEN  32

#define VTILE  64
#define NCHUNK 782           // ceil(50000/64); 50000 % 8 == 0
#define NBLK_GEMM 296        // 148 SMs x 2 blocks
#define CH_STRIDE 304

// ---- scratch (no cudaMalloc allowed) ----
__device__ float g_E[4ull*BATCH*SLEN*EMBD];   // 26.2 MB
__device__ float g_u[BATCH*EMBD];
__device__ float g_pmax[BATCH*CH_STRIDE];
__device__ float g_psum[BATCH*CH_STRIDE];
__device__ float g_lse[BATCH];
__device__ int   g_cnt;

// ============================================================
// K1: E[k][b][s][:] = sum_t A[k][x[b,s,t]]
// k-major phasing + streaming stores (proven; L2 near cap).
// ============================================================
#define SENT_PER_BLK 4
#define BLKS_PER_TBL (BATCH*SLEN/SENT_PER_BLK)   // 3200

__global__ void __launch_bounds__(128) k_embed_sum(const float* __restrict__ A,
                                                   const int* __restrict__ x) {
    int k   = blockIdx.x / BLKS_PER_TBL;
    int bs0 = (blockIdx.x % BLKS_PER_TBL) * SENT_PER_BLK;
    int tid = threadIdx.x, lane = tid & 31, w = tid >> 5;
    __shared__ int toks[SENT_PER_BLK][TLEN];
    ((int*)toks)[tid] = x[(size_t)bs0*TLEN + tid];
    __syncthreads();
    int bs = bs0 + w;
    const float4* tab = (const float4*)(A + (size_t)k*VOCAB*EMBD);
    float4 acc = make_float4(0.f,0.f,0.f,0.f);
    #pragma unroll 8
    for (int t = 0; t < TLEN; ++t) {
        float4 v = __ldg(tab + (size_t)toks[w][t]*(EMBD/4) + lane);
        acc.x += v.x; acc.y += v.y; acc.z += v.z; acc.w += v.w;
    }
    __stcs(((float4*)(g_E + ((size_t)k*BATCH*SLEN + bs)*EMBD)) + lane, acc);
}

// ============================================================
// K2: qsum + 3 hops fused, 512 threads (R10-proven). Also resets
// the gemm last-block counter (runs before k_gemm in-stream).
// ============================================================
__global__ void __launch_bounds__(512) k_hops(const float* __restrict__ A,
                                              const int* __restrict__ q,
                                              const float* __restrict__ TA,
                                              const float* __restrict__ TC) {
    int b = blockIdx.x;
    int tid = threadIdx.x, lane = tid & 31, w = tid >> 5;   // w: 0..15
    if (b == 0 && tid == 0) g_cnt = 0;
    __shared__ float su[EMBD];
    __shared__ float sp[SLEN];
    __shared__ float part[16][EMBD];
    __shared__ float red[16], red2[16];
    __shared__ float s_usum, s_max, s_sum, s_tc;

    {
        const float4* A1 = (const float4*)(A + (size_t)1*VOCAB*EMBD);
        float4 acc = make_float4(0.f,0.f,0.f,0.f);
        #pragma unroll
        for (int t = 0; t < 2; ++t) {
            int tok = q[b*QLEN + w*2 + t];
            float4 v = __ldg(A1 + (size_t)tok*(EMBD/4) + lane);
            acc.x += v.x; acc.y += v.y; acc.z += v.z; acc.w += v.w;
        }
        ((float4*)part[w])[lane] = acc;
    }
    __syncthreads();
    if (tid < EMBD) {
        float s = 0.f;
        #pragma unroll
        for (int i = 0; i < 16; ++i) s += part[i][tid];
        su[tid] = s;
    }
    __syncthreads();

    for (int k = 0; k < 3; ++k) {
        float v = (tid < EMBD) ? su[tid] : 0.f;
        #pragma unroll
        for (int o = 16; o; o >>= 1) v += __shfl_xor_sync(0xffffffffu, v, o);
        if (lane == 0) red[w] = v;
        __syncthreads();
        if (tid == 0) {
            float s = 0.f;
            #pragma unroll
            for (int i = 0; i < 16; ++i) s += red[i];
            s_usum = s;
        }
        __syncthreads();

        const float* Ek = g_E + ((size_t)k*BATCH*SLEN + (size_t)b*SLEN)*EMBD;
        const float4 u4 = ((const float4*)su)[lane];
        #pragma unroll 4
        for (int s = w; s < SLEN; s += 16) {
            float4 e4 = __ldg((const float4*)(Ek + (size_t)s*EMBD) + lane);
            float d = e4.x*u4.x + e4.y*u4.y + e4.z*u4.z + e4.w*u4.w;
            #pragma unroll
            for (int o = 16; o; o >>= 1) d += __shfl_xor_sync(0xffffffffu, d, o);
            if (lane == 0) sp[s] = d + TA[s]*s_usum;
        }
        __syncthreads();

        float sc = (tid < SLEN) ? sp[tid] : -INFINITY;
        float m = sc;
        #pragma unroll
        for (int o = 16; o; o >>= 1) m = fmaxf(m, __shfl_xor_sync(0xffffffffu, m, o));
        if (lane == 0) red[w] = m;
        __syncthreads();
        if (tid == 0) {
            float mm = red[0];
            #pragma unroll
            for (int i = 1; i < 16; ++i) mm = fmaxf(mm, red[i]);
            s_max = mm;
        }
        __syncthreads();
        float e  = (tid < SLEN) ? __expf(sc - s_max) : 0.f;
        float tc = (tid < SLEN) ? TC[tid]*e : 0.f;
        float es = e, ts = tc;
        #pragma unroll
        for (int o = 16; o; o >>= 1) {
            es += __shfl_xor_sync(0xffffffffu, es, o);
            ts += __shfl_xor_sync(0xffffffffu, ts, o);
        }
        if (lane == 0) { red[w] = es; red2[w] = ts; }
        __syncthreads();
        if (tid == 0) {
            float S = 0.f, T = 0.f;
            #pragma unroll
            for (int i = 0; i < 16; ++i) { S += red[i]; T += red2[i]; }
            s_sum = S; s_tc = T / S;
        }
        __syncthreads();
        if (tid < SLEN) sp[tid] = e / s_sum;
        __syncthreads();

        const float* Ek1 = Ek + (size_t)BATCH*SLEN*EMBD;
        float4 cacc = make_float4(0.f,0.f,0.f,0.f);
        #pragma unroll 4
        for (int s = w; s < SLEN; s += 16) {
            float4 e4 = __ldg((const float4*)(Ek1 + (size_t)s*EMBD) + lane);
            float p = sp[s];
            cacc.x += e4.x*p; cacc.y += e4.y*p; cacc.z += e4.z*p; cacc.w += e4.w*p;
        }
        ((float4*)part[w])[lane] = cacc;
        __syncthreads();
        if (tid < EMBD) {
            float t = su[tid] + s_tc;
            #pragma unroll
            for (int i = 0; i < 16; ++i) t += part[i][tid];
            su[tid] = t;
        }
        __syncthreads();
    }
    if (tid < EMBD) g_u[b*EMBD + tid] = su[tid];
}

// ============================================================
// K3: persistent GEMM — EXACT R10 mainloop (double-buffered
// cp.async, padded sU, 8v x 64b, register-running stats) + R12's
// last-block lse tail (removes the separate k_lse launch).
// ============================================================
#define FMA2(acc, a, u) asm("fma.rn.f32x2 %0, %1, %2, %0;" : "+l"(acc) : "l"(a), "l"(u))

__device__ __forceinline__ void cp_async16(uint32_t dst, const void* src) {
    asm volatile("cp.async.cg.shared.global [%0], [%1], 16;" :: "r"(dst), "l"(src));
}

__device__ __forceinline__ void lse_merge(float& M, float& S, float m2, float s2) {
    if (m2 > M) { S = S*__expf(M - m2) + s2; M = m2; }
    else        { S += s2*__expf(m2 - M); }
}

__global__ void __launch_bounds__(256) k_gemm(const float* __restrict__ A,
                                              float* __restrict__ out) {
    extern __shared__ float smem[];
    float* sU  = smem;                       // 64 x 132 padded (conflict-free)
    float* sAb[2] = { smem + 64*132, smem + 64*132 + VTILE*EMBD };
    float* pm  = smem + 64*132 + 2*VTILE*EMBD;  // 8 x 64
    float* ps  = pm + 512;

    const float* A3 = A + (size_t)3*VOCAB*EMBD;
    int tid = threadIdx.x, lane = tid & 31, w = tid >> 5;
    int b0 = lane, b1 = lane + 32;

    int tile = blockIdx.x;
    int buf = 0;
    {
        int v0 = tile*VTILE;
        #pragma unroll
        for (int i = tid; i < VTILE*32; i += 256) {
            int r = i >> 5, c = i & 31;
            cp_async16((uint32_t)__cvta_generic_to_shared(&sAb[0][r*EMBD + c*4]),
                       (const float4*)(A3 + (size_t)(v0 + r)*EMBD) + c);
        }
        asm volatile("cp.async.commit_group;");
    }

    for (int i = tid; i < 64*32; i += 256) {
        int r = i >> 5, c = i & 31;
        ((float4*)(sU + r*132))[c] = ((const float4*)g_u)[i];
    }

    float m0r = -INFINITY, m1r = -INFINITY, s0r = 0.f, s1r = 0.f;

    for (; tile < NCHUNK; tile += NBLK_GEMM) {
        int nxt = tile + NBLK_GEMM;
        if (nxt < NCHUNK) {
            int v0 = nxt*VTILE;
            #pragma unroll
            for (int i = tid; i < VTILE*32; i += 256) {
                int r = i >> 5, c = i & 31;
                int v = v0 + r; if (v >= VOCAB) v = VOCAB-1;
                cp_async16((uint32_t)__cvta_generic_to_shared(&sAb[buf^1][r*EMBD + c*4]),
                           (const float4*)(A3 + (size_t)v*EMBD) + c);
            }
            asm volatile("cp.async.commit_group;");
            asm volatile("cp.async.wait_group 1;");
        } else {
            asm volatile("cp.async.wait_group 0;");
        }
        __syncthreads();

        int vbase = tile*VTILE + w*8;
        bool valid = (vbase < VOCAB);

        unsigned long long acc0[8], acc1[8];
        #pragma unroll
        for (int j = 0; j < 8; ++j) { acc0[j] = 0ull; acc1[j] = 0ull; }

        const ulonglong2* Ua = (const ulonglong2*)(sU + b0*132);
        const ulonglong2* Ub = (const ulonglong2*)(sU + b1*132);
        const float* aBase = &sAb[buf][(w*8)*EMBD];

        #pragma unroll 2
        for (int e4 = 0; e4 < 32; ++e4) {
            ulonglong2 ua = Ua[e4];
            ulonglong2 ub = Ub[e4];
            #pragma unroll
            for (int j = 0; j < 8; ++j) {
                ulonglong2 a = ((const ulonglong2*)(aBase + j*EMBD))[e4];
                FMA2(acc0[j], a.x, ua.x);
                FMA2(acc0[j], a.y, ua.y);
                FMA2(acc1[j], a.x, ub.x);
                FMA2(acc1[j], a.y, ub.y);
            }
        }
        __syncthreads();

        float l0[8], l1[8];
        #pragma unroll
        for (int j = 0; j < 8; ++j) {
            unsigned int lo, hi;
            asm("mov.b64 {%0,%1}, %2;" : "=r"(lo), "=r"(hi) : "l"(acc0[j]));
            l0[j] = __uint_as_float(lo) + __uint_as_float(hi);
            asm("mov.b64 {%0,%1}, %2;" : "=r"(lo), "=r"(hi) : "l"(acc1[j]));
            l1[j] = __uint_as_float(lo) + __uint_as_float(hi);
        }

        if (valid) {
            float* p0 = out + (size_t)b0*VOCAB + vbase;
            float* p1 = out + (size_t)b1*VOCAB + vbase;
            ((float4*)p0)[0] = make_float4(l0[0], l0[1], l0[2], l0[3]);
            ((float4*)p0)[1] = make_float4(l0[4], l0[5], l0[6], l0[7]);
            ((float4*)p1)[0] = make_float4(l1[0], l1[1], l1[2], l1[3]);
            ((float4*)p1)[1] = make_float4(l1[4], l1[5], l1[6], l1[7]);

            float tm0 = l0[0], tm1 = l1[0];
            #pragma unroll
            for (int j = 1; j < 8; ++j) { tm0 = fmaxf(tm0, l0[j]); tm1 = fmaxf(tm1, l1[j]); }
            if (tm0 > m0r) { s0r *= __expf(m0r - tm0); m0r = tm0; }
            if (tm1 > m1r) { s1r *= __expf(m1r - tm1); m1r = tm1; }
            #pragma unroll
            for (int j = 0; j < 8; ++j) {
                s0r += __expf(l0[j] - m0r);
                s1r += __expf(l1[j] - m1r);
            }
        }
        buf ^= 1;
    }

    // per-block partial (max,sum) for each batch row
    pm[w*64 + b0] = m0r; ps[w*64 + b0] = s0r;
    pm[w*64 + b1] = m1r; ps[w*64 + b1] = s1r;
    __syncthreads();
    if (tid < 64) {
        int b = tid;
        float M = pm[b];
        #pragma unroll
        for (int i = 1; i < 8; ++i) M = fmaxf(M, pm[i*64 + b]);
        float S = 0.f;
        #pragma unroll
        for (int i = 0; i < 8; ++i) S += ps[i*64 + b]*__expf(pm[i*64 + b] - M);
        g_pmax[b*CH_STRIDE + blockIdx.x] = M;
        g_psum[b*CH_STRIDE + blockIdx.x] = S;
    }
    __threadfence();
    __syncthreads();

    // last-finishing block computes all 64 lse values (L2-hot partials)
    __shared__ int s_last;
    if (tid == 0) s_last = (atomicAdd(&g_cnt, 1) == NBLK_GEMM - 1);
    __syncthreads();
    if (s_last) {
        #pragma unroll
        for (int r = 0; r < 8; ++r) {
            int b = w*8 + r;
            float M = -1e30f, S = 0.f;
            for (int i = lane; i < NBLK_GEMM; i += 32)
                lse_merge(M, S, g_pmax[b*CH_STRIDE + i], g_psum[b*CH_STRIDE + i]);
            #pragma unroll
            for (int o = 16; o; o >>= 1) {
                float m2 = __shfl_xor_sync(0xffffffffu, M, o);
                float s2 = __shfl_xor_sync(0xffffffffu, S, o);
                lse_merge(M, S, m2, s2);
            }
            if (lane == 0) g_lse[b] = M + logf(S);
        }
    }
}

// ============================================================
// K5: out = logits - lse[b]  (in place, streaming)
// ============================================================
__global__ void __launch_bounds__(512) k_final(float* __restrict__ out) {
    size_t i = (size_t)blockIdx.x*blockDim.x + threadIdx.x;
    if (i < (size_t)BATCH*VOCAB/4) {
        int b = (int)(i / (VOCAB/4));
        float l = g_lse[b];
        float4 v = __ldcs((const float4*)out + i);
        v.x -= l; v.y -= l; v.z -= l; v.w -= l;
        __stcs((float4*)out + i, v);
    }
}

extern "C" void kernel_launch(void* const* d_in, const int* in_sizes, int n_in,
                              void* d_out, int out_size) {
    const float* A  = (const float*)d_in[0];   // [4,50000,128]
    const float* TA = (const float*)d_in[1];   // [200]
    const float* TC = (const float*)d_in[2];   // [200]
    const int*   x  = (const int*)d_in[3];     // [64,200,32]
    const int*   q  = (const int*)d_in[4];     // [64,32]
    float* out = (float*)d_out;                // [64,50000]

    k_embed_sum<<<4*BLKS_PER_TBL, 128>>>(A, x);
    k_hops<<<BATCH, 512>>>(A, q, TA, TC);

    const int smem_gemm = (64*132 + 2*VTILE*EMBD + 512 + 512) * (int)sizeof(float); // 103424 B
    cudaFuncSetAttribute(k_gemm, cudaFuncAttributeMaxDynamicSharedMemorySize, smem_gemm);
    k_gemm<<<NBLK_GEMM, 256, smem_gemm>>>(A, out);

    k_final<<<(BATCH*VOCAB/4 + 511)/512, 512>>>(out);
}

// round 17
// speedup vs baseline: 1.1173x; 1.1173x over previous
#include <cuda_runtime.h>
#include <math.h>
#include <stdint.h>

#define VOCAB 50000
#define EMBD  128
#define SLEN  200
#define TLEN  32
#define BATCH 64
#define QLEN  32

#define VTILE  64
#define NCHUNK 782           // ceil(50000/64); 50000 % 8 == 0
#define NBLK_GEMM 296        // 148 SMs x 2 blocks
#define CH_STRIDE 304

// ---- scratch (no cudaMalloc allowed) ----
__device__ float g_E[4ull*BATCH*SLEN*EMBD];   // 26.2 MB
__device__ float g_u[BATCH*EMBD];
__device__ float g_pmax[BATCH*CH_STRIDE];
__device__ float g_psum[BATCH*CH_STRIDE];
__device__ float g_lse[BATCH];

// ============================================================
// K1: E[k][b][s][:] = sum_t A[k][x[b,s,t]]
// k-major phasing + streaming stores (proven; L2 near cap).
// ============================================================
#define SENT_PER_BLK 4
#define BLKS_PER_TBL (BATCH*SLEN/SENT_PER_BLK)   // 3200

__global__ void __launch_bounds__(128) k_embed_sum(const float* __restrict__ A,
                                                   const int* __restrict__ x) {
    int k   = blockIdx.x / BLKS_PER_TBL;
    int bs0 = (blockIdx.x % BLKS_PER_TBL) * SENT_PER_BLK;
    int tid = threadIdx.x, lane = tid & 31, w = tid >> 5;
    __shared__ int toks[SENT_PER_BLK][TLEN];
    ((int*)toks)[tid] = x[(size_t)bs0*TLEN + tid];
    __syncthreads();
    int bs = bs0 + w;
    const float4* tab = (const float4*)(A + (size_t)k*VOCAB*EMBD);
    float4 acc = make_float4(0.f,0.f,0.f,0.f);
    #pragma unroll 8
    for (int t = 0; t < TLEN; ++t) {
        float4 v = __ldg(tab + (size_t)toks[w][t]*(EMBD/4) + lane);
        acc.x += v.x; acc.y += v.y; acc.z += v.z; acc.w += v.w;
    }
    __stcs(((float4*)(g_E + ((size_t)k*BATCH*SLEN + bs)*EMBD)) + lane, acc);
}

// ============================================================
// K2: qsum + 3 hops fused, 512 threads (R10-proven).
// ============================================================
__global__ void __launch_bounds__(512) k_hops(const float* __restrict__ A,
                                              const int* __restrict__ q,
                                              const float* __restrict__ TA,
                                              const float* __restrict__ TC) {
    int b = blockIdx.x;
    int tid = threadIdx.x, lane = tid & 31, w = tid >> 5;   // w: 0..15
    __shared__ float su[EMBD];
    __shared__ float sp[SLEN];
    __shared__ float part[16][EMBD];
    __shared__ float red[16], red2[16];
    __shared__ float s_usum, s_max, s_sum, s_tc;

    {
        const float4* A1 = (const float4*)(A + (size_t)1*VOCAB*EMBD);
        float4 acc = make_float4(0.f,0.f,0.f,0.f);
        #pragma unroll
        for (int t = 0; t < 2; ++t) {
            int tok = q[b*QLEN + w*2 + t];
            float4 v = __ldg(A1 + (size_t)tok*(EMBD/4) + lane);
            acc.x += v.x; acc.y += v.y; acc.z += v.z; acc.w += v.w;
        }
        ((float4*)part[w])[lane] = acc;
    }
    __syncthreads();
    if (tid < EMBD) {
        float s = 0.f;
        #pragma unroll
        for (int i = 0; i < 16; ++i) s += part[i][tid];
        su[tid] = s;
    }
    __syncthreads();

    for (int k = 0; k < 3; ++k) {
        float v = (tid < EMBD) ? su[tid] : 0.f;
        #pragma unroll
        for (int o = 16; o; o >>= 1) v += __shfl_xor_sync(0xffffffffu, v, o);
        if (lane == 0) red[w] = v;
        __syncthreads();
        if (tid == 0) {
            float s = 0.f;
            #pragma unroll
            for (int i = 0; i < 16; ++i) s += red[i];
            s_usum = s;
        }
        __syncthreads();

        const float* Ek = g_E + ((size_t)k*BATCH*SLEN + (size_t)b*SLEN)*EMBD;
        const float4 u4 = ((const float4*)su)[lane];
        #pragma unroll 4
        for (int s = w; s < SLEN; s += 16) {
            float4 e4 = __ldg((const float4*)(Ek + (size_t)s*EMBD) + lane);
            float d = e4.x*u4.x + e4.y*u4.y + e4.z*u4.z + e4.w*u4.w;
            #pragma unroll
            for (int o = 16; o; o >>= 1) d += __shfl_xor_sync(0xffffffffu, d, o);
            if (lane == 0) sp[s] = d + TA[s]*s_usum;
        }
        __syncthreads();

        float sc = (tid < SLEN) ? sp[tid] : -INFINITY;
        float m = sc;
        #pragma unroll
        for (int o = 16; o; o >>= 1) m = fmaxf(m, __shfl_xor_sync(0xffffffffu, m, o));
        if (lane == 0) red[w] = m;
        __syncthreads();
        if (tid == 0) {
            float mm = red[0];
            #pragma unroll
            for (int i = 1; i < 16; ++i) mm = fmaxf(mm, red[i]);
            s_max = mm;
        }
        __syncthreads();
        float e  = (tid < SLEN) ? __expf(sc - s_max) : 0.f;
        float tc = (tid < SLEN) ? TC[tid]*e : 0.f;
        float es = e, ts = tc;
        #pragma unroll
        for (int o = 16; o; o >>= 1) {
            es += __shfl_xor_sync(0xffffffffu, es, o);
            ts += __shfl_xor_sync(0xffffffffu, ts, o);
        }
        if (lane == 0) { red[w] = es; red2[w] = ts; }
        __syncthreads();
        if (tid == 0) {
            float S = 0.f, T = 0.f;
            #pragma unroll
            for (int i = 0; i < 16; ++i) { S += red[i]; T += red2[i]; }
            s_sum = S; s_tc = T / S;
        }
        __syncthreads();
        if (tid < SLEN) sp[tid] = e / s_sum;
        __syncthreads();

        const float* Ek1 = Ek + (size_t)BATCH*SLEN*EMBD;
        float4 cacc = make_float4(0.f,0.f,0.f,0.f);
        #pragma unroll 4
        for (int s = w; s < SLEN; s += 16) {
            float4 e4 = __ldg((const float4*)(Ek1 + (size_t)s*EMBD) + lane);
            float p = sp[s];
            cacc.x += e4.x*p; cacc.y += e4.y*p; cacc.z += e4.z*p; cacc.w += e4.w*p;
        }
        ((float4*)part[w])[lane] = cacc;
        __syncthreads();
        if (tid < EMBD) {
            float t = su[tid] + s_tc;
            #pragma unroll
            for (int i = 0; i < 16; ++i) t += part[i][tid];
            su[tid] = t;
        }
        __syncthreads();
    }
    if (tid < EMBD) g_u[b*EMBD + tid] = su[tid];
}

// ============================================================
// K3: persistent GEMM — EXACT R10 mainloop (double-buffered
// cp.async, padded sU, 8v x 64b, register-running stats).
// Only delta vs R10: __stcs on logit stores (protect A3 in L2).
// NO in-kernel lse tail (proven -13us toxic in R12/R13).
// ============================================================
#define FMA2(acc, a, u) asm("fma.rn.f32x2 %0, %1, %2, %0;" : "+l"(acc) : "l"(a), "l"(u))

__device__ __forceinline__ void cp_async16(uint32_t dst, const void* src) {
    asm volatile("cp.async.cg.shared.global [%0], [%1], 16;" :: "r"(dst), "l"(src));
}

__global__ void __launch_bounds__(256) k_gemm(const float* __restrict__ A,
                                              float* __restrict__ out) {
    extern __shared__ float smem[];
    float* sU  = smem;                       // 64 x 132 padded (conflict-free)
    float* sAb[2] = { smem + 64*132, smem + 64*132 + VTILE*EMBD };
    float* pm  = smem + 64*132 + 2*VTILE*EMBD;  // 8 x 64
    float* ps  = pm + 512;

    const float* A3 = A + (size_t)3*VOCAB*EMBD;
    int tid = threadIdx.x, lane = tid & 31, w = tid >> 5;
    int b0 = lane, b1 = lane + 32;

    int tile = blockIdx.x;
    int buf = 0;
    {
        int v0 = tile*VTILE;
        #pragma unroll
        for (int i = tid; i < VTILE*32; i += 256) {
            int r = i >> 5, c = i & 31;
            cp_async16((uint32_t)__cvta_generic_to_shared(&sAb[0][r*EMBD + c*4]),
                       (const float4*)(A3 + (size_t)(v0 + r)*EMBD) + c);
        }
        asm volatile("cp.async.commit_group;");
    }

    for (int i = tid; i < 64*32; i += 256) {
        int r = i >> 5, c = i & 31;
        ((float4*)(sU + r*132))[c] = ((const float4*)g_u)[i];
    }

    float m0r = -INFINITY, m1r = -INFINITY, s0r = 0.f, s1r = 0.f;

    for (; tile < NCHUNK; tile += NBLK_GEMM) {
        int nxt = tile + NBLK_GEMM;
        if (nxt < NCHUNK) {
            int v0 = nxt*VTILE;
            #pragma unroll
            for (int i = tid; i < VTILE*32; i += 256) {
                int r = i >> 5, c = i & 31;
                int v = v0 + r; if (v >= VOCAB) v = VOCAB-1;
                cp_async16((uint32_t)__cvta_generic_to_shared(&sAb[buf^1][r*EMBD + c*4]),
                           (const float4*)(A3 + (size_t)v*EMBD) + c);
            }
            asm volatile("cp.async.commit_group;");
            asm volatile("cp.async.wait_group 1;");
        } else {
            asm volatile("cp.async.wait_group 0;");
        }
        __syncthreads();

        int vbase = tile*VTILE + w*8;
        bool valid = (vbase < VOCAB);

        unsigned long long acc0[8], acc1[8];
        #pragma unroll
        for (int j = 0; j < 8; ++j) { acc0[j] = 0ull; acc1[j] = 0ull; }

        const ulonglong2* Ua = (const ulonglong2*)(sU + b0*132);
        const ulonglong2* Ub = (const ulonglong2*)(sU + b1*132);
        const float* aBase = &sAb[buf][(w*8)*EMBD];

        #pragma unroll 2
        for (int e4 = 0; e4 < 32; ++e4) {
            ulonglong2 ua = Ua[e4];
            ulonglong2 ub = Ub[e4];
            #pragma unroll
            for (int j = 0; j < 8; ++j) {
                ulonglong2 a = ((const ulonglong2*)(aBase + j*EMBD))[e4];
                FMA2(acc0[j], a.x, ua.x);
                FMA2(acc0[j], a.y, ua.y);
                FMA2(acc1[j], a.x, ub.x);
                FMA2(acc1[j], a.y, ub.y);
            }
        }
        __syncthreads();

        float l0[8], l1[8];
        #pragma unroll
        for (int j = 0; j < 8; ++j) {
            unsigned int lo, hi;
            asm("mov.b64 {%0,%1}, %2;" : "=r"(lo), "=r"(hi) : "l"(acc0[j]));
            l0[j] = __uint_as_float(lo) + __uint_as_float(hi);
            asm("mov.b64 {%0,%1}, %2;" : "=r"(lo), "=r"(hi) : "l"(acc1[j]));
            l1[j] = __uint_as_float(lo) + __uint_as_float(hi);
        }

        if (valid) {
            float* p0 = out + (size_t)b0*VOCAB + vbase;
            float* p1 = out + (size_t)b1*VOCAB + vbase;
            __stcs((float4*)p0,     make_float4(l0[0], l0[1], l0[2], l0[3]));
            __stcs((float4*)p0 + 1, make_float4(l0[4], l0[5], l0[6], l0[7]));
            __stcs((float4*)p1,     make_float4(l1[0], l1[1], l1[2], l1[3]));
            __stcs((float4*)p1 + 1, make_float4(l1[4], l1[5], l1[6], l1[7]));

            float tm0 = l0[0], tm1 = l1[0];
            #pragma unroll
            for (int j = 1; j < 8; ++j) { tm0 = fmaxf(tm0, l0[j]); tm1 = fmaxf(tm1, l1[j]); }
            if (tm0 > m0r) { s0r *= __expf(m0r - tm0); m0r = tm0; }
            if (tm1 > m1r) { s1r *= __expf(m1r - tm1); m1r = tm1; }
            #pragma unroll
            for (int j = 0; j < 8; ++j) {
                s0r += __expf(l0[j] - m0r);
                s1r += __expf(l1[j] - m1r);
            }
        }
        buf ^= 1;
    }

    pm[w*64 + b0] = m0r; ps[w*64 + b0] = s0r;
    pm[w*64 + b1] = m1r; ps[w*64 + b1] = s1r;
    __syncthreads();
    if (tid < 64) {
        int b = tid;
        float M = pm[b];
        #pragma unroll
        for (int i = 1; i < 8; ++i) M = fmaxf(M, pm[i*64 + b]);
        float S = 0.f;
        #pragma unroll
        for (int i = 0; i < 8; ++i) S += ps[i*64 + b]*__expf(pm[i*64 + b] - M);
        g_pmax[b*CH_STRIDE + blockIdx.x] = M;
        g_psum[b*CH_STRIDE + blockIdx.x] = S;
    }
}

// ============================================================
// K4: combine per-block partials -> lse[b] (R10 version).
// ============================================================
__device__ __forceinline__ void lse_merge(float& M, float& S, float m2, float s2) {
    if (m2 > M) { S = S*__expf(M - m2) + s2; M = m2; }
    else        { S += s2*__expf(m2 - M); }
}

__global__ void __launch_bounds__(256) k_lse() {
    int b = blockIdx.x, tid = threadIdx.x, lane = tid & 31, w = tid >> 5;
    __shared__ float sm[8], ss[8];
    float M = -1e30f, S = 0.f;
    for (int i = tid; i < NBLK_GEMM; i += 256)
        lse_merge(M, S, g_pmax[b*CH_STRIDE + i], g_psum[b*CH_STRIDE + i]);
    #pragma unroll
    for (int o = 16; o; o >>= 1) {
        float m2 = __shfl_xor_sync(0xffffffffu, M, o);
        float s2 = __shfl_xor_sync(0xffffffffu, S, o);
        lse_merge(M, S, m2, s2);
    }
    if (lane == 0) { sm[w] = M; ss[w] = S; }
    __syncthreads();
    if (tid == 0) {
        float Mf = sm[0], Sf = ss[0];
        #pragma unroll
        for (int i = 1; i < 8; ++i) lse_merge(Mf, Sf, sm[i], ss[i]);
        g_lse[b] = Mf + logf(Sf);
    }
}

// ============================================================
// K5: out = logits - lse[b]  (in place, streaming; R10 version)
// ============================================================
__global__ void __launch_bounds__(512) k_final(float* __restrict__ out) {
    size_t i = (size_t)blockIdx.x*blockDim.x + threadIdx.x;
    if (i < (size_t)BATCH*VOCAB/4) {
        int b = (int)(i / (VOCAB/4));
        float l = g_lse[b];
        float4 v = __ldcs((const float4*)out + i);
        v.x -= l; v.y -= l; v.z -= l; v.w -= l;
        __stcs((float4*)out + i, v);
    }
}

extern "C" void kernel_launch(void* const* d_in, const int* in_sizes, int n_in,
                              void* d_out, int out_size) {
    const float* A  = (const float*)d_in[0];   // [4,50000,128]
    const float* TA = (const float*)d_in[1];   // [200]
    const float* TC = (const float*)d_in[2];   // [200]
    const int*   x  = (const int*)d_in[3];     // [64,200,32]
    const int*   q  = (const int*)d_in[4];     // [64,32]
    float* out = (float*)d_out;                // [64,50000]

    k_embed_sum<<<4*BLKS_PER_TBL, 128>>>(A, x);
    k_hops<<<BATCH, 512>>>(A, q, TA, TC);

    const int smem_gemm = (64*132 + 2*VTILE*EMBD + 512 + 512) * (int)sizeof(float); // 103424 B
    cudaFuncSetAttribute(k_gemm, cudaFuncAttributeMaxDynamicSharedMemorySize, smem_gemm);
    k_gemm<<<NBLK_GEMM, 256, smem_gemm>>>(A, out);

    k_lse<<<BATCH, 256>>>();
    k_final<<<(BATCH*VOCAB/4 + 511)/512, 512>>>(out);
}